// round 16
// baseline (speedup 1.0000x reference)
#include <cuda_runtime.h>
#include <cuda_fp16.h>
#include <math.h>
#include <stdint.h>

static constexpr int MAXN = 100000;
static constexpr int MAXE = 1600000;
static constexpr int F1   = 128;   // F_in and H*HID
static constexpr int F2   = 160;   // H*NCLS
static constexpr int NH   = 4;
static constexpr float NEG_SLOPE = 0.2f;

typedef unsigned long long ull;

// ---------------- scratch ----------------------------------------------------
__device__ ull   g_h1h [(size_t)MAXN * F1 / 4];   // fp16 h1
__device__ ull   g_h2h [(size_t)MAXN * F2 / 4];   // fp16 h2
__device__ ull   g_o1h [(size_t)MAXN * F1 / 4];   // fp16 layer-1 output
__device__ float g_als1[(size_t)MAXN * NH];
__device__ float g_ald1[(size_t)MAXN * NH];
__device__ float g_als2[(size_t)MAXN * NH];
__device__ float g_ald2[(size_t)MAXN * NH];
__device__ int   g_cnt [2 * MAXN];
__device__ int   g_rowp[MAXN + 1];
__device__ int   g_col [MAXE];
__device__ ull   g_state[256];
__device__ int   g_ticket;
__device__ uint32_t g_wp1[128 * F1];   // fragment-packed tf32 W1
__device__ uint32_t g_wp2[128 * F2];   // fragment-packed tf32 W2

__device__ __forceinline__ float lrelu(float v) {
    return v > 0.f ? v : NEG_SLOPE * v;
}

__device__ __forceinline__ uint32_t f2tf32(float f) {
    uint32_t u;
    asm("cvt.rna.tf32.f32 %0, %1;" : "=r"(u) : "f"(f));
    return u;
}

__device__ __forceinline__ void mma_tf32(float& c0, float& c1, float& c2, float& c3,
                                         uint32_t a0, uint32_t a1, uint32_t a2, uint32_t a3,
                                         uint32_t b0, uint32_t b1) {
    asm volatile(
        "mma.sync.aligned.m16n8k8.row.col.f32.tf32.tf32.f32 "
        "{%0,%1,%2,%3}, {%4,%5,%6,%7}, {%8,%9}, {%0,%1,%2,%3};"
        : "+f"(c0), "+f"(c1), "+f"(c2), "+f"(c3)
        : "r"(a0), "r"(a1), "r"(a2), "r"(a3), "r"(b0), "r"(b1));
}

// packed f32x2 helpers (FFMA2)
__device__ __forceinline__ ull packf2(float a, float b) {
    ull r; asm("mov.b64 %0, {%1, %2};" : "=l"(r) : "f"(a), "f"(b)); return r;
}
__device__ __forceinline__ void fma2p(ull& d, ull a, ull b) {
    asm("fma.rn.f32x2 %0, %1, %2, %0;" : "+l"(d) : "l"(a), "l"(b));
}
__device__ __forceinline__ float2 unpackf2(ull v) {
    float2 f; asm("mov.b64 {%0, %1}, %2;" : "=f"(f.x), "=f"(f.y) : "l"(v)); return f;
}
// half2 -> packed f32x2
__device__ __forceinline__ ull h2tof2(uint32_t h2) {
    float2 f = __half22float2(*reinterpret_cast<__half2*>(&h2));
    return packf2(f.x, f.y);
}
// accumulate uint4 (8 halves) scaled by e into 4 packed accumulators
__device__ __forceinline__ void acc_h16x8p(ull* acc, uint4 u, ull ep) {
    fma2p(acc[0], ep, h2tof2(u.x));
    fma2p(acc[1], ep, h2tof2(u.y));
    fma2p(acc[2], ep, h2tof2(u.z));
    fma2p(acc[3], ep, h2tof2(u.w));
}

// ---------------- CSR build --------------------------------------------------
__global__ void count_deg(const int* __restrict__ dst, int* __restrict__ cnt, int E) {
    int e = blockIdx.x * blockDim.x + threadIdx.x;
    if (e < E) atomicAdd(&cnt[dst[e]], 1);
}

static constexpr ull FLG_AGG = 1ull << 62;
static constexpr ull FLG_PRE = 2ull << 62;

__global__ void scan_one(const int* __restrict__ cnt, int* __restrict__ rowp,
                         int* __restrict__ cnt2,
                         ull* __restrict__ state, int* __restrict__ ticket,
                         int N, int E)
{
    __shared__ int sm[512];
    __shared__ int sbid, sprefix;
    int t = threadIdx.x;
    if (t == 0) sbid = atomicAdd(ticket, 1);
    __syncthreads();
    int b = sbid;
    int i = b * 512 + t;
    int v = (i < N) ? cnt[i] : 0;
    sm[t] = v;
    __syncthreads();
    for (int o = 1; o < 512; o <<= 1) {
        int add = (t >= o) ? sm[t - o] : 0;
        __syncthreads();
        sm[t] += add;
        __syncthreads();
    }
    int incl  = sm[t];
    int total = sm[511];
    if (t == 0) {
        if (b == 0) {
            atomicExch(&state[0], FLG_PRE | (unsigned)total);
            sprefix = 0;
        } else {
            atomicExch(&state[b], FLG_AGG | (unsigned)total);
            int run = 0, j = b - 1;
            while (true) {
                ull s;
                do { s = atomicAdd(&state[j], 0ull); } while ((s >> 62) == 0);
                run += (int)(s & 0xffffffffu);
                if (s & FLG_PRE) break;
                --j;
            }
            atomicExch(&state[b], FLG_PRE | (unsigned)(run + total));
            sprefix = run;
        }
    }
    __syncthreads();
    if (i < N) {
        int off = sprefix + incl - v;
        rowp[i] = off;
        cnt2[i] = off;
    }
    if (b == 0 && t == 0) rowp[N] = E;
}

// two edges per thread: batched loads + paired atomics (2x atomic MLP)
__global__ void fill_csr(const int* __restrict__ src, const int* __restrict__ dst,
                         int* __restrict__ cnt2, int* __restrict__ col, int E) {
    int base = (blockIdx.x * blockDim.x + threadIdx.x) * 2;
    if (base >= E) return;
    if (base + 1 < E) {
        int d0 = __ldg(dst + base), d1 = __ldg(dst + base + 1);
        int s0 = __ldg(src + base), s1 = __ldg(src + base + 1);
        int k0 = atomicAdd(&cnt2[d0], 1);
        int k1 = atomicAdd(&cnt2[d1], 1);
        col[k0] = s0;
        col[k1] = s1;
    } else {
        int d0 = __ldg(dst + base);
        int k0 = atomicAdd(&cnt2[d0], 1);
        col[k0] = __ldg(src + base);
    }
}

// ---------------- one-shot W pack --------------------------------------------
template<int NOUT>
__global__ void pack_w(const float* __restrict__ W, uint32_t* __restrict__ out)
{
    constexpr int JJ = NOUT / 32;
    int i = blockIdx.x * blockDim.x + threadIdx.x;
    if (i >= 128 * NOUT / 4) return;
    int idx = i * 4;
    int kk  = idx / NOUT;
    int cc  = idx % NOUT;
    float4 v = *reinterpret_cast<const float4*>(W + (size_t)kk * NOUT + cc);
    int kb  = kk >> 3;
    int km  = kk & 7;
    int tg2 = km & 3;
    int b01 = km >> 2;
    int wc  = cc / (NOUT / 2);
    int nn  = cc % (NOUT / 2);
    int jj  = nn >> 4;
    int rem = nn & 15;
    int jpar = rem >> 3;
    int gq  = rem & 7;
    int quad = jpar * 2 + b01;
    uint32_t base = (uint32_t)((kb * 2 + wc) * JJ + jj) * 32;
    float vv[4] = {v.x, v.y, v.z, v.w};
#pragma unroll
    for (int j = 0; j < 4; ++j) {
        int lp = ((gq + j) * 4 + tg2) & 31;
        out[(base + lp) * 4 + quad] = f2tf32(vv[j]);
    }
}

// ---------------- GEMM (mma.sync tf32) + fused attention epilogue ------------
template<int NOUT, bool RELU_BIAS, bool AHALF>
__global__ void __launch_bounds__(256, 3)
gemm_mma(const void* __restrict__ Ap,
         const uint32_t* __restrict__ WP,
         const float* __restrict__ bias,
         const float* __restrict__ a_s,
         const float* __restrict__ a_d,
         __half* __restrict__ outh,
         float* __restrict__ als,
         float* __restrict__ ald, int N)
{
    constexpr int NTILE = NOUT / 16;
    constexpr int JJ    = NOUT / 32;
    constexpr int HALF  = NTILE / 2;
    extern __shared__ uint32_t usmem[];
    uint32_t* sA   = usmem;
    float*    sAls = reinterpret_cast<float*>(usmem + 64 * 128);
    float*    sAld = sAls + 256;

    const int tid  = threadIdx.x;
    const int warp = tid >> 5;
    const int lane = tid & 31;
    const int g    = lane >> 2;
    const int tg   = lane & 3;
    const int warp_r = warp & 3;
    const int warp_c = warp >> 2;
    const int r0   = warp_r * 16;
    const int row0 = blockIdx.x * 64;
    const int nbase = warp_c * (NOUT / 2);

    for (int i = tid; i < 512; i += 256) { sAls[i] = 0.f; }

    if (!AHALF) {
        const float* A = (const float*)Ap;
        for (int i = tid; i < 64 * 128 / 4; i += 256) {
            int idx = i * 4;
            int r   = idx >> 7;
            int k   = idx & 127;
            int gr  = row0 + r;
            float4 v = make_float4(0.f, 0.f, 0.f, 0.f);
            if (gr < N) {
                v = *reinterpret_cast<const float4*>(A + (size_t)gr * 128 + k);
                if (RELU_BIAS) {
                    v.x = fmaxf(v.x + bias[k + 0], 0.f);
                    v.y = fmaxf(v.y + bias[k + 1], 0.f);
                    v.z = fmaxf(v.z + bias[k + 2], 0.f);
                    v.w = fmaxf(v.w + bias[k + 3], 0.f);
                }
            }
            int rw    = r >> 4;
            int rr    = r & 15;
            int gq    = rr & 7;
            int rowhi = rr >> 3;
            int kb    = k >> 3;
            int khi   = (k >> 2) & 1;
            int slot  = khi * 2 + rowhi;
            uint32_t base = (uint32_t)(rw * 16 + kb) * 32;
            int lpb  = gq * 4 + kb * 5;
            float vv[4] = {v.x, v.y, v.z, v.w};
#pragma unroll
            for (int j = 0; j < 4; ++j)
                sA[(base + ((lpb + j) & 31)) * 4 + slot] = f2tf32(vv[j]);
        }
    } else {
        const __half* A = (const __half*)Ap;
        for (int i = tid; i < 64 * 128 / 8; i += 256) {
            int idx = i * 8;
            int r   = idx >> 7;
            int k   = idx & 127;
            int gr  = row0 + r;
            float f[8];
            if (gr < N) {
                uint4 u = *reinterpret_cast<const uint4*>(A + (size_t)gr * 128 + k);
                float2 p0 = __half22float2(*reinterpret_cast<__half2*>(&u.x));
                float2 p1 = __half22float2(*reinterpret_cast<__half2*>(&u.y));
                float2 p2 = __half22float2(*reinterpret_cast<__half2*>(&u.z));
                float2 p3 = __half22float2(*reinterpret_cast<__half2*>(&u.w));
                f[0] = p0.x; f[1] = p0.y; f[2] = p1.x; f[3] = p1.y;
                f[4] = p2.x; f[5] = p2.y; f[6] = p3.x; f[7] = p3.y;
                if (RELU_BIAS) {
#pragma unroll
                    for (int j = 0; j < 8; ++j)
                        f[j] = fmaxf(f[j] + __ldg(bias + k + j), 0.f);
                }
            } else {
#pragma unroll
                for (int j = 0; j < 8; ++j) f[j] = 0.f;
            }
            int rw    = r >> 4;
            int rr    = r & 15;
            int gq    = rr & 7;
            int rowhi = rr >> 3;
            int kb    = k >> 3;
            uint32_t base = (uint32_t)(rw * 16 + kb) * 32;
            int lpb  = gq * 4 + kb * 5;
#pragma unroll
            for (int j = 0; j < 8; ++j) {
                int slot = (j >> 2) * 2 + rowhi;
                sA[(base + ((lpb + (j & 3)) & 31)) * 4 + slot] = f2tf32(f[j]);
            }
        }
    }
    __syncthreads();

    float c[NTILE][4];
#pragma unroll
    for (int j = 0; j < NTILE; ++j) {
        c[j][0] = 0.f; c[j][1] = 0.f; c[j][2] = 0.f; c[j][3] = 0.f;
    }

    const uint4* wp4 = reinterpret_cast<const uint4*>(WP);

#pragma unroll
    for (int kb = 0; kb < 16; ++kb) {
        int laneA = (lane + kb * 5) & 31;
        uint4 av = *reinterpret_cast<uint4*>(
            sA + ((uint32_t)(warp_r * 16 + kb) * 32 + laneA) * 4);
        const uint4* wrow = wp4 + (uint32_t)((kb * 2 + warp_c) * JJ) * 32 + lane;
#pragma unroll
        for (int jj = 0; jj < JJ; ++jj) {
            uint4 bv = __ldg(wrow + jj * 32);
            mma_tf32(c[2*jj][0], c[2*jj][1], c[2*jj][2], c[2*jj][3],
                     av.x, av.y, av.z, av.w, bv.x, bv.y);
            mma_tf32(c[2*jj+1][0], c[2*jj+1][1], c[2*jj+1][2], c[2*jj+1][3],
                     av.x, av.y, av.z, av.w, bv.z, bv.w);
        }
    }

    int rA = row0 + r0 + g;
    int rB = rA + 8;
    float pa[2][2] = {{0.f, 0.f}, {0.f, 0.f}};
    float pd[2][2] = {{0.f, 0.f}, {0.f, 0.f}};
#pragma unroll
    for (int j = 0; j < NTILE; ++j) {
        int colp = nbase + j * 8 + 2 * tg;
        if (rA < N)
            *reinterpret_cast<__half2*>(outh + (size_t)rA * NOUT + colp) =
                __floats2half2_rn(c[j][0], c[j][1]);
        if (rB < N)
            *reinterpret_cast<__half2*>(outh + (size_t)rB * NOUT + colp) =
                __floats2half2_rn(c[j][2], c[j][3]);
        float2 asv = __ldg(reinterpret_cast<const float2*>(a_s + colp));
        float2 adv = __ldg(reinterpret_cast<const float2*>(a_d + colp));
        int hsel = j / HALF;
        pa[hsel][0] += c[j][0] * asv.x + c[j][1] * asv.y;
        pa[hsel][1] += c[j][2] * asv.x + c[j][3] * asv.y;
        pd[hsel][0] += c[j][0] * adv.x + c[j][1] * adv.y;
        pd[hsel][1] += c[j][2] * adv.x + c[j][3] * adv.y;
    }
    int raL = r0 + g;
    int rbL = raL + 8;
    int h0 = 2 * warp_c;
#pragma unroll
    for (int hs = 0; hs < 2; ++hs) {
        atomicAdd(&sAls[raL * 4 + h0 + hs], pa[hs][0]);
        atomicAdd(&sAls[rbL * 4 + h0 + hs], pa[hs][1]);
        atomicAdd(&sAld[raL * 4 + h0 + hs], pd[hs][0]);
        atomicAdd(&sAld[rbL * 4 + h0 + hs], pd[hs][1]);
    }
    __syncthreads();

    if (tid < 256) {
        int r = tid >> 2;
        int gr = row0 + r;
        if (gr < N) {
            als[(size_t)gr * 4 + (tid & 3)] = sAls[tid];
            ald[(size_t)gr * 4 + (tid & 3)] = sAld[tid];
        }
    }
}

// ---------------- layer-1 aggregation: 2 nodes per warp, FFMA2, fp16 out -----
__global__ void aggregate_csr_128(const int* __restrict__ rowp,
                                  const int* __restrict__ col,
                                  const float* __restrict__ als,
                                  const float* __restrict__ ald,
                                  const __half* __restrict__ Hh,
                                  __half* __restrict__ outh, int N)
{
    int w    = (int)((blockIdx.x * (size_t)blockDim.x + threadIdx.x) >> 5);
    int lane = threadIdx.x & 31;
    int hw   = lane >> 4;
    int hl   = lane & 15;
    int n = w * 2 + hw;
    if (n >= N) return;
    int head = hl >> 2;
    float ald_h = __ldg(ald + (size_t)n * 4 + head);
    int beg = __ldg(rowp + n), end = __ldg(rowp + n + 1);

    ull acc[4] = {0ull, 0ull, 0ull, 0ull};
    float den = 0.f;

    int i = beg;
    for (; i + 4 <= end; i += 4) {
        int s0 = __ldg(col + i),     s1 = __ldg(col + i + 1);
        int s2 = __ldg(col + i + 2), s3 = __ldg(col + i + 3);
        float al0 = __ldg(als + (size_t)s0 * 4 + head);
        float al1 = __ldg(als + (size_t)s1 * 4 + head);
        float al2 = __ldg(als + (size_t)s2 * 4 + head);
        float al3 = __ldg(als + (size_t)s3 * 4 + head);
        uint4 u0 = *reinterpret_cast<const uint4*>(Hh + (size_t)s0 * 128 + hl * 8);
        uint4 u1 = *reinterpret_cast<const uint4*>(Hh + (size_t)s1 * 128 + hl * 8);
        uint4 u2 = *reinterpret_cast<const uint4*>(Hh + (size_t)s2 * 128 + hl * 8);
        uint4 u3 = *reinterpret_cast<const uint4*>(Hh + (size_t)s3 * 128 + hl * 8);
        float e0 = __expf(lrelu(al0 + ald_h));
        float e1 = __expf(lrelu(al1 + ald_h));
        float e2 = __expf(lrelu(al2 + ald_h));
        float e3 = __expf(lrelu(al3 + ald_h));
        acc_h16x8p(acc, u0, packf2(e0, e0));
        acc_h16x8p(acc, u1, packf2(e1, e1));
        acc_h16x8p(acc, u2, packf2(e2, e2));
        acc_h16x8p(acc, u3, packf2(e3, e3));
        den += (e0 + e1) + (e2 + e3);
    }
    for (; i < end; ++i) {
        int s0 = __ldg(col + i);
        float e0 = __expf(lrelu(__ldg(als + (size_t)s0 * 4 + head) + ald_h));
        uint4 u0 = *reinterpret_cast<const uint4*>(Hh + (size_t)s0 * 128 + hl * 8);
        acc_h16x8p(acc, u0, packf2(e0, e0));
        den += e0;
    }
    float inv = 1.f / (den + 1e-16f);
    float2 f0 = unpackf2(acc[0]);
    float2 f1 = unpackf2(acc[1]);
    float2 f2 = unpackf2(acc[2]);
    float2 f3 = unpackf2(acc[3]);
    uint4 o;
    *reinterpret_cast<__half2*>(&o.x) = __floats2half2_rn(f0.x * inv, f0.y * inv);
    *reinterpret_cast<__half2*>(&o.y) = __floats2half2_rn(f1.x * inv, f1.y * inv);
    *reinterpret_cast<__half2*>(&o.z) = __floats2half2_rn(f2.x * inv, f2.y * inv);
    *reinterpret_cast<__half2*>(&o.w) = __floats2half2_rn(f3.x * inv, f3.y * inv);
    *reinterpret_cast<uint4*>(outh + (size_t)n * 128 + hl * 8) = o;
}

// ---------------- layer-2 aggregation + head-mean + log_softmax (FFMA2) ------
__global__ void aggregate_csr_160_final(const int* __restrict__ rowp,
                                        const int* __restrict__ col,
                                        const float* __restrict__ als,
                                        const float* __restrict__ ald,
                                        const __half* __restrict__ Hh,
                                        const float* __restrict__ b2,
                                        float* __restrict__ y, int N)
{
    __shared__ __align__(16) float sbuf[8][160];
    int wid  = threadIdx.x >> 5;
    int n    = (int)((blockIdx.x * (size_t)blockDim.x + threadIdx.x) >> 5);
    int lane = threadIdx.x & 31;
    if (n >= N) return;
    bool act = (lane < 20);
    int head = act ? (lane / 5) : 0;
    float ald_h = __ldg(ald + (size_t)n * 4 + head);
    int beg = __ldg(rowp + n), end = __ldg(rowp + n + 1);

    ull acc[4] = {0ull, 0ull, 0ull, 0ull};
    float den = 0.f;
    const uint4 uz = make_uint4(0u, 0u, 0u, 0u);

    int i = beg;
    for (; i + 4 <= end; i += 4) {
        int s0 = __ldg(col + i),     s1 = __ldg(col + i + 1);
        int s2 = __ldg(col + i + 2), s3 = __ldg(col + i + 3);
        float al0 = __ldg(als + (size_t)s0 * 4 + head);
        float al1 = __ldg(als + (size_t)s1 * 4 + head);
        float al2 = __ldg(als + (size_t)s2 * 4 + head);
        float al3 = __ldg(als + (size_t)s3 * 4 + head);
        uint4 u0 = act ? *reinterpret_cast<const uint4*>(Hh + (size_t)s0 * 160 + lane * 8) : uz;
        uint4 u1 = act ? *reinterpret_cast<const uint4*>(Hh + (size_t)s1 * 160 + lane * 8) : uz;
        uint4 u2 = act ? *reinterpret_cast<const uint4*>(Hh + (size_t)s2 * 160 + lane * 8) : uz;
        uint4 u3 = act ? *reinterpret_cast<const uint4*>(Hh + (size_t)s3 * 160 + lane * 8) : uz;
        float e0 = __expf(lrelu(al0 + ald_h));
        float e1 = __expf(lrelu(al1 + ald_h));
        float e2 = __expf(lrelu(al2 + ald_h));
        float e3 = __expf(lrelu(al3 + ald_h));
        acc_h16x8p(acc, u0, packf2(e0, e0));
        acc_h16x8p(acc, u1, packf2(e1, e1));
        acc_h16x8p(acc, u2, packf2(e2, e2));
        acc_h16x8p(acc, u3, packf2(e3, e3));
        den += (e0 + e1) + (e2 + e3);
    }
    for (; i < end; ++i) {
        int s0 = __ldg(col + i);
        float e0 = __expf(lrelu(__ldg(als + (size_t)s0 * 4 + head) + ald_h));
        uint4 u0 = act ? *reinterpret_cast<const uint4*>(Hh + (size_t)s0 * 160 + lane * 8) : uz;
        acc_h16x8p(acc, u0, packf2(e0, e0));
        den += e0;
    }
    float inv = 1.f / (den + 1e-16f);
    if (act) {
        float2 f0 = unpackf2(acc[0]);
        float2 f1 = unpackf2(acc[1]);
        float2 f2 = unpackf2(acc[2]);
        float2 f3 = unpackf2(acc[3]);
        *reinterpret_cast<float4*>(&sbuf[wid][lane * 8]) =
            make_float4(f0.x * inv, f0.y * inv, f1.x * inv, f1.y * inv);
        *reinterpret_cast<float4*>(&sbuf[wid][lane * 8 + 4]) =
            make_float4(f2.x * inv, f2.y * inv, f3.x * inv, f3.y * inv);
    }
    __syncwarp();

    const float* S = sbuf[wid];
    int c0 = lane;
    int c1 = lane + 32;
    bool has1 = (c1 < 40);

    float v0 = 0.25f * (S[c0] + S[40 + c0] + S[80 + c0] + S[120 + c0]) + __ldg(&b2[c0]);
    float v1 = -1e30f;
    if (has1)
        v1 = 0.25f * (S[c1] + S[40 + c1] + S[80 + c1] + S[120 + c1]) + __ldg(&b2[c1]);

    float m = fmaxf(v0, v1);
#pragma unroll
    for (int o = 16; o; o >>= 1) m = fmaxf(m, __shfl_xor_sync(0xffffffffu, m, o));
    float se = __expf(v0 - m) + (has1 ? __expf(v1 - m) : 0.f);
#pragma unroll
    for (int o = 16; o; o >>= 1) se += __shfl_xor_sync(0xffffffffu, se, o);
    float lse = logf(se) + m;

    y[(size_t)n * 40 + c0] = v0 - lse;
    if (has1) y[(size_t)n * 40 + c1] = v1 - lse;
}

// ---------------- host side --------------------------------------------------
extern "C" void kernel_launch(void* const* d_in, const int* in_sizes, int n_in,
                              void* d_out, int out_size)
{
    const float* x   = (const float*)d_in[0];
    const int*   ei  = (const int*)  d_in[1];
    const float* W1  = (const float*)d_in[2];
    const float* as1 = (const float*)d_in[3];
    const float* ad1 = (const float*)d_in[4];
    const float* b1  = (const float*)d_in[5];
    const float* W2  = (const float*)d_in[6];
    const float* as2 = (const float*)d_in[7];
    const float* ad2 = (const float*)d_in[8];
    const float* b2  = (const float*)d_in[9];
    float* y = (float*)d_out;

    const int N = in_sizes[0] / F1;
    const int E = in_sizes[1] / 2;
    const int* src = ei;
    const int* dst = ei + E;

    void* p;
    cudaGetSymbolAddress(&p, g_h1h);   __half* h1h = (__half*)p;
    cudaGetSymbolAddress(&p, g_h2h);   __half* h2h = (__half*)p;
    cudaGetSymbolAddress(&p, g_o1h);   __half* o1h = (__half*)p;
    cudaGetSymbolAddress(&p, g_als1);  float* als1 = (float*)p;
    cudaGetSymbolAddress(&p, g_ald1);  float* ald1 = (float*)p;
    cudaGetSymbolAddress(&p, g_als2);  float* als2 = (float*)p;
    cudaGetSymbolAddress(&p, g_ald2);  float* ald2 = (float*)p;
    cudaGetSymbolAddress(&p, g_cnt);   int* cnt  = (int*)p;
    cudaGetSymbolAddress(&p, g_rowp);  int* rowp = (int*)p;
    cudaGetSymbolAddress(&p, g_col);   int* col  = (int*)p;
    cudaGetSymbolAddress(&p, g_state); ull* state = (ull*)p;
    cudaGetSymbolAddress(&p, g_ticket); int* ticket = (int*)p;
    cudaGetSymbolAddress(&p, g_wp1);   uint32_t* wp1 = (uint32_t*)p;
    cudaGetSymbolAddress(&p, g_wp2);   uint32_t* wp2 = (uint32_t*)p;
    int* cnt2 = cnt + MAXN;

    static cudaStream_t s2 = nullptr;
    static cudaEvent_t evFork = nullptr, evJoin = nullptr;
    if (!s2) {
        cudaStreamCreateWithFlags(&s2, cudaStreamNonBlocking);
        cudaEventCreateWithFlags(&evFork, cudaEventDisableTiming);
        cudaEventCreateWithFlags(&evJoin, cudaEventDisableTiming);
    }

    const int smem = (64 * 128 + 512) * 4;   // 34 KB
    cudaFuncSetAttribute(gemm_mma<F1, false, false>,
                         cudaFuncAttributeMaxDynamicSharedMemorySize, smem);
    cudaFuncSetAttribute(gemm_mma<F2, true, true>,
                         cudaFuncAttributeMaxDynamicSharedMemorySize, smem);

    const int TB = 256;
    const int NB = (N + 511) / 512;
    const int gemmBlocks   = (N + 63) / 64;
    const int nodeWBlocks  = (int)(((size_t)N * 32 + TB - 1) / TB);
    const int node2WBlocks = (int)((((size_t)(N + 1) / 2) * 32 + TB - 1) / TB);

    cudaMemsetAsync(cnt, 0, (size_t)MAXN * sizeof(int));
    cudaMemsetAsync(state, 0, 256 * sizeof(ull));
    cudaMemsetAsync(ticket, 0, sizeof(int));

    // fork: CSR build + W2 pack on s2, concurrent with gemm1
    cudaEventRecord(evFork, 0);
    cudaStreamWaitEvent(s2, evFork, 0);

    pack_w<F2><<<(128 * F2 / 4 + TB - 1) / TB, TB, 0, s2>>>(W2, wp2);
    count_deg<<<(E + TB - 1) / TB, TB, 0, s2>>>(dst, cnt, E);
    scan_one<<<NB, 512, 0, s2>>>(cnt, rowp, cnt2, state, ticket, N, E);
    fill_csr<<<(E / 2 + TB - 1) / TB + 1, TB, 0, s2>>>(src, dst, cnt2, col, E);
    cudaEventRecord(evJoin, s2);

    // main stream: pack W1, then layer-1 GEMM (+ fused attention)
    pack_w<F1><<<(128 * F1 / 4 + TB - 1) / TB, TB>>>(W1, wp1);
    gemm_mma<F1, false, false><<<gemmBlocks, TB, smem>>>(
        x, wp1, nullptr, as1, ad1, h1h, als1, ald1, N);

    cudaStreamWaitEvent(0, evJoin, 0);

    aggregate_csr_128<<<node2WBlocks, TB>>>(rowp, col, als1, ald1, h1h, o1h, N);

    gemm_mma<F2, true, true><<<gemmBlocks, TB, smem>>>(
        o1h, wp2, b1, as2, ad2, h2h, als2, ald2, N);

    aggregate_csr_160_final<<<nodeWBlocks, TB>>>(rowp, col, als2, ald2, h2h, b2, y, N);
}

// round 17
// speedup vs baseline: 1.0576x; 1.0576x over previous
#include <cuda_runtime.h>
#include <cuda_fp16.h>
#include <math.h>
#include <stdint.h>

static constexpr int MAXN = 100000;
static constexpr int MAXE = 1600000;
static constexpr int F1   = 128;   // F_in and H*HID
static constexpr int F2   = 160;   // H*NCLS
static constexpr int NH   = 4;
static constexpr float NEG_SLOPE = 0.2f;

typedef unsigned long long ull;

// ---------------- scratch ----------------------------------------------------
__device__ ull   g_h1h [(size_t)MAXN * F1 / 4];   // fp16 h1
__device__ ull   g_h2h [(size_t)MAXN * F2 / 4];   // fp16 h2
__device__ ull   g_o1h [(size_t)MAXN * F1 / 4];   // fp16 layer-1 output
__device__ float g_als1[(size_t)MAXN * NH];
__device__ float g_ald1[(size_t)MAXN * NH];
__device__ float g_als2[(size_t)MAXN * NH];
__device__ float g_ald2[(size_t)MAXN * NH];
__device__ int   g_cnt [2 * MAXN];
__device__ int   g_rowp[MAXN + 1];
__device__ int   g_col [MAXE];
__device__ ull   g_state[256];
__device__ int   g_ticket;
__device__ uint32_t g_wp1[128 * F1];   // fragment-packed tf32 W1
__device__ uint32_t g_wp2[128 * F2];   // fragment-packed tf32 W2

__device__ __forceinline__ float lrelu(float v) {
    return v > 0.f ? v : NEG_SLOPE * v;
}

__device__ __forceinline__ uint32_t f2tf32(float f) {
    uint32_t u;
    asm("cvt.rna.tf32.f32 %0, %1;" : "=r"(u) : "f"(f));
    return u;
}

__device__ __forceinline__ void mma_tf32(float& c0, float& c1, float& c2, float& c3,
                                         uint32_t a0, uint32_t a1, uint32_t a2, uint32_t a3,
                                         uint32_t b0, uint32_t b1) {
    asm volatile(
        "mma.sync.aligned.m16n8k8.row.col.f32.tf32.tf32.f32 "
        "{%0,%1,%2,%3}, {%4,%5,%6,%7}, {%8,%9}, {%0,%1,%2,%3};"
        : "+f"(c0), "+f"(c1), "+f"(c2), "+f"(c3)
        : "r"(a0), "r"(a1), "r"(a2), "r"(a3), "r"(b0), "r"(b1));
}

// ---------------- CSR build --------------------------------------------------
__global__ void count_deg(const int* __restrict__ dst, int* __restrict__ cnt, int E) {
    int e = blockIdx.x * blockDim.x + threadIdx.x;
    if (e < E) atomicAdd(&cnt[dst[e]], 1);
}

static constexpr ull FLG_AGG = 1ull << 62;
static constexpr ull FLG_PRE = 2ull << 62;

// scan also seeds cnt2 with the row-start offsets, so fill_csr's atomicAdd
// return value is the absolute col[] position (no rowp gather needed).
__global__ void scan_one(const int* __restrict__ cnt, int* __restrict__ rowp,
                         int* __restrict__ cnt2,
                         ull* __restrict__ state, int* __restrict__ ticket,
                         int N, int E)
{
    __shared__ int sm[512];
    __shared__ int sbid, sprefix;
    int t = threadIdx.x;
    if (t == 0) sbid = atomicAdd(ticket, 1);
    __syncthreads();
    int b = sbid;
    int i = b * 512 + t;
    int v = (i < N) ? cnt[i] : 0;
    sm[t] = v;
    __syncthreads();
    for (int o = 1; o < 512; o <<= 1) {
        int add = (t >= o) ? sm[t - o] : 0;
        __syncthreads();
        sm[t] += add;
        __syncthreads();
    }
    int incl  = sm[t];
    int total = sm[511];
    if (t == 0) {
        if (b == 0) {
            atomicExch(&state[0], FLG_PRE | (unsigned)total);
            sprefix = 0;
        } else {
            atomicExch(&state[b], FLG_AGG | (unsigned)total);
            int run = 0, j = b - 1;
            while (true) {
                ull s;
                do { s = atomicAdd(&state[j], 0ull); } while ((s >> 62) == 0);
                run += (int)(s & 0xffffffffu);
                if (s & FLG_PRE) break;
                --j;
            }
            atomicExch(&state[b], FLG_PRE | (unsigned)(run + total));
            sprefix = run;
        }
    }
    __syncthreads();
    if (i < N) {
        int off = sprefix + incl - v;
        rowp[i] = off;
        cnt2[i] = off;
    }
    if (b == 0 && t == 0) rowp[N] = E;
}

__global__ void fill_csr(const int* __restrict__ src, const int* __restrict__ dst,
                         int* __restrict__ cnt2, int* __restrict__ col, int E) {
    int e = blockIdx.x * blockDim.x + threadIdx.x;
    if (e >= E) return;
    int d = __ldg(dst + e);
    int k = atomicAdd(&cnt2[d], 1);
    col[k] = __ldg(src + e);
}

// ---------------- one-shot W pack --------------------------------------------
template<int NOUT>
__global__ void pack_w(const float* __restrict__ W, uint32_t* __restrict__ out)
{
    constexpr int JJ = NOUT / 32;
    int i = blockIdx.x * blockDim.x + threadIdx.x;
    if (i >= 128 * NOUT / 4) return;
    int idx = i * 4;
    int kk  = idx / NOUT;
    int cc  = idx % NOUT;
    float4 v = *reinterpret_cast<const float4*>(W + (size_t)kk * NOUT + cc);
    int kb  = kk >> 3;
    int km  = kk & 7;
    int tg2 = km & 3;
    int b01 = km >> 2;
    int wc  = cc / (NOUT / 2);
    int nn  = cc % (NOUT / 2);
    int jj  = nn >> 4;
    int rem = nn & 15;
    int jpar = rem >> 3;
    int gq  = rem & 7;
    int quad = jpar * 2 + b01;
    uint32_t base = (uint32_t)((kb * 2 + wc) * JJ + jj) * 32;
    float vv[4] = {v.x, v.y, v.z, v.w};
#pragma unroll
    for (int j = 0; j < 4; ++j) {
        int lp = ((gq + j) * 4 + tg2) & 31;
        out[(base + lp) * 4 + quad] = f2tf32(vv[j]);
    }
}

// ---------------- GEMM (mma.sync tf32) + fused attention epilogue ------------
template<int NOUT, bool RELU_BIAS, bool AHALF>
__global__ void __launch_bounds__(256, 3)
gemm_mma(const void* __restrict__ Ap,
         const uint32_t* __restrict__ WP,
         const float* __restrict__ bias,
         const float* __restrict__ a_s,
         const float* __restrict__ a_d,
         __half* __restrict__ outh,
         float* __restrict__ als,
         float* __restrict__ ald, int N)
{
    constexpr int NTILE = NOUT / 16;
    constexpr int JJ    = NOUT / 32;
    constexpr int HALF  = NTILE / 2;
    extern __shared__ uint32_t usmem[];
    uint32_t* sA   = usmem;
    float*    sAls = reinterpret_cast<float*>(usmem + 64 * 128);   // [64][4]
    float*    sAld = sAls + 256;                                    // [64][4]

    const int tid  = threadIdx.x;
    const int warp = tid >> 5;
    const int lane = tid & 31;
    const int g    = lane >> 2;
    const int tg   = lane & 3;
    const int warp_r = warp & 3;
    const int warp_c = warp >> 2;
    const int r0   = warp_r * 16;
    const int row0 = blockIdx.x * 64;
    const int nbase = warp_c * (NOUT / 2);

    for (int i = tid; i < 512; i += 256) { sAls[i] = 0.f; }

    if (!AHALF) {
        const float* A = (const float*)Ap;
        for (int i = tid; i < 64 * 128 / 4; i += 256) {
            int idx = i * 4;
            int r   = idx >> 7;
            int k   = idx & 127;
            int gr  = row0 + r;
            float4 v = make_float4(0.f, 0.f, 0.f, 0.f);
            if (gr < N) {
                v = *reinterpret_cast<const float4*>(A + (size_t)gr * 128 + k);
                if (RELU_BIAS) {
                    v.x = fmaxf(v.x + bias[k + 0], 0.f);
                    v.y = fmaxf(v.y + bias[k + 1], 0.f);
                    v.z = fmaxf(v.z + bias[k + 2], 0.f);
                    v.w = fmaxf(v.w + bias[k + 3], 0.f);
                }
            }
            int rw    = r >> 4;
            int rr    = r & 15;
            int gq    = rr & 7;
            int rowhi = rr >> 3;
            int kb    = k >> 3;
            int khi   = (k >> 2) & 1;
            int slot  = khi * 2 + rowhi;
            uint32_t base = (uint32_t)(rw * 16 + kb) * 32;
            int lpb  = gq * 4 + kb * 5;
            float vv[4] = {v.x, v.y, v.z, v.w};
#pragma unroll
            for (int j = 0; j < 4; ++j)
                sA[(base + ((lpb + j) & 31)) * 4 + slot] = f2tf32(vv[j]);
        }
    } else {
        const __half* A = (const __half*)Ap;
        for (int i = tid; i < 64 * 128 / 8; i += 256) {
            int idx = i * 8;
            int r   = idx >> 7;
            int k   = idx & 127;          // multiple of 8 == kb*8
            int gr  = row0 + r;
            float f[8];
            if (gr < N) {
                uint4 u = *reinterpret_cast<const uint4*>(A + (size_t)gr * 128 + k);
                float2 p0 = __half22float2(*reinterpret_cast<__half2*>(&u.x));
                float2 p1 = __half22float2(*reinterpret_cast<__half2*>(&u.y));
                float2 p2 = __half22float2(*reinterpret_cast<__half2*>(&u.z));
                float2 p3 = __half22float2(*reinterpret_cast<__half2*>(&u.w));
                f[0] = p0.x; f[1] = p0.y; f[2] = p1.x; f[3] = p1.y;
                f[4] = p2.x; f[5] = p2.y; f[6] = p3.x; f[7] = p3.y;
                if (RELU_BIAS) {
#pragma unroll
                    for (int j = 0; j < 8; ++j)
                        f[j] = fmaxf(f[j] + __ldg(bias + k + j), 0.f);
                }
            } else {
#pragma unroll
                for (int j = 0; j < 8; ++j) f[j] = 0.f;
            }
            int rw    = r >> 4;
            int rr    = r & 15;
            int gq    = rr & 7;
            int rowhi = rr >> 3;
            int kb    = k >> 3;
            uint32_t base = (uint32_t)(rw * 16 + kb) * 32;
            int lpb  = gq * 4 + kb * 5;
#pragma unroll
            for (int j = 0; j < 8; ++j) {
                int slot = (j >> 2) * 2 + rowhi;
                sA[(base + ((lpb + (j & 3)) & 31)) * 4 + slot] = f2tf32(f[j]);
            }
        }
    }
    __syncthreads();

    float c[NTILE][4];
#pragma unroll
    for (int j = 0; j < NTILE; ++j) {
        c[j][0] = 0.f; c[j][1] = 0.f; c[j][2] = 0.f; c[j][3] = 0.f;
    }

    const uint4* wp4 = reinterpret_cast<const uint4*>(WP);

#pragma unroll
    for (int kb = 0; kb < 16; ++kb) {
        int laneA = (lane + kb * 5) & 31;
        uint4 av = *reinterpret_cast<uint4*>(
            sA + ((uint32_t)(warp_r * 16 + kb) * 32 + laneA) * 4);
        const uint4* wrow = wp4 + (uint32_t)((kb * 2 + warp_c) * JJ) * 32 + lane;
#pragma unroll
        for (int jj = 0; jj < JJ; ++jj) {
            uint4 bv = __ldg(wrow + jj * 32);
            mma_tf32(c[2*jj][0], c[2*jj][1], c[2*jj][2], c[2*jj][3],
                     av.x, av.y, av.z, av.w, bv.x, bv.y);
            mma_tf32(c[2*jj+1][0], c[2*jj+1][1], c[2*jj+1][2], c[2*jj+1][3],
                     av.x, av.y, av.z, av.w, bv.z, bv.w);
        }
    }

    // ---- store C as fp16 + accumulate attention partials ----
    int rA = row0 + r0 + g;
    int rB = rA + 8;
    float pa[2][2] = {{0.f, 0.f}, {0.f, 0.f}};
    float pd[2][2] = {{0.f, 0.f}, {0.f, 0.f}};
#pragma unroll
    for (int j = 0; j < NTILE; ++j) {
        int colp = nbase + j * 8 + 2 * tg;
        if (rA < N)
            *reinterpret_cast<__half2*>(outh + (size_t)rA * NOUT + colp) =
                __floats2half2_rn(c[j][0], c[j][1]);
        if (rB < N)
            *reinterpret_cast<__half2*>(outh + (size_t)rB * NOUT + colp) =
                __floats2half2_rn(c[j][2], c[j][3]);
        float2 asv = __ldg(reinterpret_cast<const float2*>(a_s + colp));
        float2 adv = __ldg(reinterpret_cast<const float2*>(a_d + colp));
        int hsel = j / HALF;
        pa[hsel][0] += c[j][0] * asv.x + c[j][1] * asv.y;
        pa[hsel][1] += c[j][2] * asv.x + c[j][3] * asv.y;
        pd[hsel][0] += c[j][0] * adv.x + c[j][1] * adv.y;
        pd[hsel][1] += c[j][2] * adv.x + c[j][3] * adv.y;
    }
    int raL = r0 + g;
    int rbL = raL + 8;
    int h0 = 2 * warp_c;
#pragma unroll
    for (int hs = 0; hs < 2; ++hs) {
        atomicAdd(&sAls[raL * 4 + h0 + hs], pa[hs][0]);
        atomicAdd(&sAls[rbL * 4 + h0 + hs], pa[hs][1]);
        atomicAdd(&sAld[raL * 4 + h0 + hs], pd[hs][0]);
        atomicAdd(&sAld[rbL * 4 + h0 + hs], pd[hs][1]);
    }
    __syncthreads();

    if (tid < 256) {
        int r = tid >> 2;
        int gr = row0 + r;
        if (gr < N) {
            als[(size_t)gr * 4 + (tid & 3)] = sAls[tid];
            ald[(size_t)gr * 4 + (tid & 3)] = sAld[tid];
        }
    }
}

// ---------------- layer-1 aggregation: 2 nodes per warp, fp16 out ------------
__device__ __forceinline__ void acc_h16x8(float4& p, float4& q, uint4 u, float e) {
    float2 f0 = __half22float2(*reinterpret_cast<__half2*>(&u.x));
    float2 f1 = __half22float2(*reinterpret_cast<__half2*>(&u.y));
    float2 f2 = __half22float2(*reinterpret_cast<__half2*>(&u.z));
    float2 f3 = __half22float2(*reinterpret_cast<__half2*>(&u.w));
    p.x = fmaf(e, f0.x, p.x); p.y = fmaf(e, f0.y, p.y);
    p.z = fmaf(e, f1.x, p.z); p.w = fmaf(e, f1.y, p.w);
    q.x = fmaf(e, f2.x, q.x); q.y = fmaf(e, f2.y, q.y);
    q.z = fmaf(e, f3.x, q.z); q.w = fmaf(e, f3.y, q.w);
}

__global__ void aggregate_csr_128(const int* __restrict__ rowp,
                                  const int* __restrict__ col,
                                  const float* __restrict__ als,
                                  const float* __restrict__ ald,
                                  const __half* __restrict__ Hh,
                                  __half* __restrict__ outh, int N)
{
    int w    = (int)((blockIdx.x * (size_t)blockDim.x + threadIdx.x) >> 5);
    int lane = threadIdx.x & 31;
    int hw   = lane >> 4;
    int hl   = lane & 15;
    int n = w * 2 + hw;
    if (n >= N) return;
    int head = hl >> 2;
    float ald_h = __ldg(ald + (size_t)n * 4 + head);
    int beg = __ldg(rowp + n), end = __ldg(rowp + n + 1);

    float4 accP = make_float4(0.f, 0.f, 0.f, 0.f);
    float4 accQ = make_float4(0.f, 0.f, 0.f, 0.f);
    float den = 0.f;

    int i = beg;
    for (; i + 4 <= end; i += 4) {
        int s0 = __ldg(col + i),     s1 = __ldg(col + i + 1);
        int s2 = __ldg(col + i + 2), s3 = __ldg(col + i + 3);
        float al0 = __ldg(als + (size_t)s0 * 4 + head);
        float al1 = __ldg(als + (size_t)s1 * 4 + head);
        float al2 = __ldg(als + (size_t)s2 * 4 + head);
        float al3 = __ldg(als + (size_t)s3 * 4 + head);
        uint4 u0 = *reinterpret_cast<const uint4*>(Hh + (size_t)s0 * 128 + hl * 8);
        uint4 u1 = *reinterpret_cast<const uint4*>(Hh + (size_t)s1 * 128 + hl * 8);
        uint4 u2 = *reinterpret_cast<const uint4*>(Hh + (size_t)s2 * 128 + hl * 8);
        uint4 u3 = *reinterpret_cast<const uint4*>(Hh + (size_t)s3 * 128 + hl * 8);
        float e0 = __expf(lrelu(al0 + ald_h));
        float e1 = __expf(lrelu(al1 + ald_h));
        float e2 = __expf(lrelu(al2 + ald_h));
        float e3 = __expf(lrelu(al3 + ald_h));
        acc_h16x8(accP, accQ, u0, e0);
        acc_h16x8(accP, accQ, u1, e1);
        acc_h16x8(accP, accQ, u2, e2);
        acc_h16x8(accP, accQ, u3, e3);
        den += (e0 + e1) + (e2 + e3);
    }
    for (; i < end; ++i) {
        int s0 = __ldg(col + i);
        float e0 = __expf(lrelu(__ldg(als + (size_t)s0 * 4 + head) + ald_h));
        uint4 u0 = *reinterpret_cast<const uint4*>(Hh + (size_t)s0 * 128 + hl * 8);
        acc_h16x8(accP, accQ, u0, e0);
        den += e0;
    }
    float inv = 1.f / (den + 1e-16f);
    uint4 o;
    *reinterpret_cast<__half2*>(&o.x) = __floats2half2_rn(accP.x * inv, accP.y * inv);
    *reinterpret_cast<__half2*>(&o.y) = __floats2half2_rn(accP.z * inv, accP.w * inv);
    *reinterpret_cast<__half2*>(&o.z) = __floats2half2_rn(accQ.x * inv, accQ.y * inv);
    *reinterpret_cast<__half2*>(&o.w) = __floats2half2_rn(accQ.z * inv, accQ.w * inv);
    *reinterpret_cast<uint4*>(outh + (size_t)n * 128 + hl * 8) = o;
}

// ---------------- layer-2 aggregation + head-mean + log_softmax --------------
__global__ void aggregate_csr_160_final(const int* __restrict__ rowp,
                                        const int* __restrict__ col,
                                        const float* __restrict__ als,
                                        const float* __restrict__ ald,
                                        const __half* __restrict__ Hh,
                                        const float* __restrict__ b2,
                                        float* __restrict__ y, int N)
{
    __shared__ __align__(16) float sbuf[8][160];
    int wid  = threadIdx.x >> 5;
    int n    = (int)((blockIdx.x * (size_t)blockDim.x + threadIdx.x) >> 5);
    int lane = threadIdx.x & 31;
    if (n >= N) return;
    bool act = (lane < 20);
    int head = act ? (lane / 5) : 0;
    float ald_h = __ldg(ald + (size_t)n * 4 + head);
    int beg = __ldg(rowp + n), end = __ldg(rowp + n + 1);

    float4 accP = make_float4(0.f, 0.f, 0.f, 0.f);
    float4 accQ = make_float4(0.f, 0.f, 0.f, 0.f);
    float den = 0.f;
    const uint4 uz = make_uint4(0u, 0u, 0u, 0u);

    int i = beg;
    for (; i + 4 <= end; i += 4) {
        int s0 = __ldg(col + i),     s1 = __ldg(col + i + 1);
        int s2 = __ldg(col + i + 2), s3 = __ldg(col + i + 3);
        float al0 = __ldg(als + (size_t)s0 * 4 + head);
        float al1 = __ldg(als + (size_t)s1 * 4 + head);
        float al2 = __ldg(als + (size_t)s2 * 4 + head);
        float al3 = __ldg(als + (size_t)s3 * 4 + head);
        uint4 u0 = act ? *reinterpret_cast<const uint4*>(Hh + (size_t)s0 * 160 + lane * 8) : uz;
        uint4 u1 = act ? *reinterpret_cast<const uint4*>(Hh + (size_t)s1 * 160 + lane * 8) : uz;
        uint4 u2 = act ? *reinterpret_cast<const uint4*>(Hh + (size_t)s2 * 160 + lane * 8) : uz;
        uint4 u3 = act ? *reinterpret_cast<const uint4*>(Hh + (size_t)s3 * 160 + lane * 8) : uz;
        float e0 = __expf(lrelu(al0 + ald_h));
        float e1 = __expf(lrelu(al1 + ald_h));
        float e2 = __expf(lrelu(al2 + ald_h));
        float e3 = __expf(lrelu(al3 + ald_h));
        acc_h16x8(accP, accQ, u0, e0);
        acc_h16x8(accP, accQ, u1, e1);
        acc_h16x8(accP, accQ, u2, e2);
        acc_h16x8(accP, accQ, u3, e3);
        den += (e0 + e1) + (e2 + e3);
    }
    for (; i < end; ++i) {
        int s0 = __ldg(col + i);
        float e0 = __expf(lrelu(__ldg(als + (size_t)s0 * 4 + head) + ald_h));
        uint4 u0 = act ? *reinterpret_cast<const uint4*>(Hh + (size_t)s0 * 160 + lane * 8) : uz;
        acc_h16x8(accP, accQ, u0, e0);
        den += e0;
    }
    float inv = 1.f / (den + 1e-16f);
    if (act) {
        *reinterpret_cast<float4*>(&sbuf[wid][lane * 8]) =
            make_float4(accP.x * inv, accP.y * inv, accP.z * inv, accP.w * inv);
        *reinterpret_cast<float4*>(&sbuf[wid][lane * 8 + 4]) =
            make_float4(accQ.x * inv, accQ.y * inv, accQ.z * inv, accQ.w * inv);
    }
    __syncwarp();

    const float* S = sbuf[wid];
    int c0 = lane;
    int c1 = lane + 32;
    bool has1 = (c1 < 40);

    float v0 = 0.25f * (S[c0] + S[40 + c0] + S[80 + c0] + S[120 + c0]) + __ldg(&b2[c0]);
    float v1 = -1e30f;
    if (has1)
        v1 = 0.25f * (S[c1] + S[40 + c1] + S[80 + c1] + S[120 + c1]) + __ldg(&b2[c1]);

    float m = fmaxf(v0, v1);
#pragma unroll
    for (int o = 16; o; o >>= 1) m = fmaxf(m, __shfl_xor_sync(0xffffffffu, m, o));
    float se = __expf(v0 - m) + (has1 ? __expf(v1 - m) : 0.f);
#pragma unroll
    for (int o = 16; o; o >>= 1) se += __shfl_xor_sync(0xffffffffu, se, o);
    float lse = logf(se) + m;

    y[(size_t)n * 40 + c0] = v0 - lse;
    if (has1) y[(size_t)n * 40 + c1] = v1 - lse;
}

// ---------------- host side --------------------------------------------------
extern "C" void kernel_launch(void* const* d_in, const int* in_sizes, int n_in,
                              void* d_out, int out_size)
{
    const float* x   = (const float*)d_in[0];
    const int*   ei  = (const int*)  d_in[1];
    const float* W1  = (const float*)d_in[2];
    const float* as1 = (const float*)d_in[3];
    const float* ad1 = (const float*)d_in[4];
    const float* b1  = (const float*)d_in[5];
    const float* W2  = (const float*)d_in[6];
    const float* as2 = (const float*)d_in[7];
    const float* ad2 = (const float*)d_in[8];
    const float* b2  = (const float*)d_in[9];
    float* y = (float*)d_out;

    const int N = in_sizes[0] / F1;
    const int E = in_sizes[1] / 2;
    const int* src = ei;
    const int* dst = ei + E;

    void* p;
    cudaGetSymbolAddress(&p, g_h1h);   __half* h1h = (__half*)p;
    cudaGetSymbolAddress(&p, g_h2h);   __half* h2h = (__half*)p;
    cudaGetSymbolAddress(&p, g_o1h);   __half* o1h = (__half*)p;
    cudaGetSymbolAddress(&p, g_als1);  float* als1 = (float*)p;
    cudaGetSymbolAddress(&p, g_ald1);  float* ald1 = (float*)p;
    cudaGetSymbolAddress(&p, g_als2);  float* als2 = (float*)p;
    cudaGetSymbolAddress(&p, g_ald2);  float* ald2 = (float*)p;
    cudaGetSymbolAddress(&p, g_cnt);   int* cnt  = (int*)p;
    cudaGetSymbolAddress(&p, g_rowp);  int* rowp = (int*)p;
    cudaGetSymbolAddress(&p, g_col);   int* col  = (int*)p;
    cudaGetSymbolAddress(&p, g_state); ull* state = (ull*)p;
    cudaGetSymbolAddress(&p, g_ticket); int* ticket = (int*)p;
    cudaGetSymbolAddress(&p, g_wp1);   uint32_t* wp1 = (uint32_t*)p;
    cudaGetSymbolAddress(&p, g_wp2);   uint32_t* wp2 = (uint32_t*)p;
    int* cnt2 = cnt + MAXN;

    static cudaStream_t s2 = nullptr;
    static cudaEvent_t evFork = nullptr, evJoin = nullptr;
    if (!s2) {
        cudaStreamCreateWithFlags(&s2, cudaStreamNonBlocking);
        cudaEventCreateWithFlags(&evFork, cudaEventDisableTiming);
        cudaEventCreateWithFlags(&evJoin, cudaEventDisableTiming);
    }

    const int smem = (64 * 128 + 512) * 4;   // 34 KB
    cudaFuncSetAttribute(gemm_mma<F1, false, false>,
                         cudaFuncAttributeMaxDynamicSharedMemorySize, smem);
    cudaFuncSetAttribute(gemm_mma<F2, true, true>,
                         cudaFuncAttributeMaxDynamicSharedMemorySize, smem);

    const int TB = 256;
    const int NB = (N + 511) / 512;
    const int gemmBlocks   = (N + 63) / 64;
    const int nodeWBlocks  = (int)(((size_t)N * 32 + TB - 1) / TB);
    const int node2WBlocks = (int)((((size_t)(N + 1) / 2) * 32 + TB - 1) / TB);

    cudaMemsetAsync(cnt, 0, (size_t)MAXN * sizeof(int));   // cnt only; cnt2 seeded by scan
    cudaMemsetAsync(state, 0, 256 * sizeof(ull));
    cudaMemsetAsync(ticket, 0, sizeof(int));

    // fork: CSR build on s2 (pack_w2 moved off this branch), concurrent with gemm1
    cudaEventRecord(evFork, 0);
    cudaStreamWaitEvent(s2, evFork, 0);

    count_deg<<<(E + TB - 1) / TB, TB, 0, s2>>>(dst, cnt, E);
    scan_one<<<NB, 512, 0, s2>>>(cnt, rowp, cnt2, state, ticket, N, E);
    fill_csr<<<(E + TB - 1) / TB, TB, 0, s2>>>(src, dst, cnt2, col, E);
    cudaEventRecord(evJoin, s2);

    // main stream: pack W1, layer-1 GEMM, then pack W2 (hidden before the join)
    pack_w<F1><<<(128 * F1 / 4 + TB - 1) / TB, TB>>>(W1, wp1);
    gemm_mma<F1, false, false><<<gemmBlocks, TB, smem>>>(
        x, wp1, nullptr, as1, ad1, h1h, als1, ald1, N);
    pack_w<F2><<<(128 * F2 / 4 + TB - 1) / TB, TB>>>(W2, wp2);

    cudaStreamWaitEvent(0, evJoin, 0);

    aggregate_csr_128<<<node2WBlocks, TB>>>(rowp, col, als1, ald1, h1h, o1h, N);

    gemm_mma<F2, true, true><<<gemmBlocks, TB, smem>>>(
        o1h, wp2, b1, as2, ad2, h2h, als2, ald2, N);

    aggregate_csr_160_final<<<nodeWBlocks, TB>>>(rowp, col, als2, ald2, h2h, b2, y, N);
}